// round 1
// baseline (speedup 1.0000x reference)
#include <cuda_runtime.h>
#include <cstdint>
#include <math.h>

// ---------------------------------------------------------------------------
// GIN_Net forward on GB300 (sm_103a), fp32 baseline.
//   agg1 = x + scatter_sum(x[src] -> dst)
//   h    = elu(relu(agg1 @ w1a + b1a) @ w1b + b1b)
//   agg2 = h + scatter_sum(h[src] -> dst)
//   out  = relu(agg2 @ w2a + b2a) @ w2b + b2b
//   output = [out (N*C) | Q (E/2*C)]
// ---------------------------------------------------------------------------

#define MAX_N 100000
#define HDIM  128

// scratch (alloc-free rule: device globals)
__device__ float g_buf0[MAX_N * HDIM];
__device__ float g_buf1[MAX_N * HDIM];

// ---------------- f32x2 packed-math helpers (FFMA2 only via PTX) -----------
__device__ __forceinline__ unsigned long long pack2(float lo, float hi) {
    unsigned long long r;
    asm("mov.b64 %0, {%1, %2};" : "=l"(r) : "f"(lo), "f"(hi));
    return r;
}
__device__ __forceinline__ unsigned long long fma2(unsigned long long a,
                                                   unsigned long long b,
                                                   unsigned long long c) {
    unsigned long long d;
    asm("fma.rn.f32x2 %0, %1, %2, %3;" : "=l"(d) : "l"(a), "l"(b), "l"(c));
    return d;
}
__device__ __forceinline__ void unpack2(unsigned long long v, float& lo, float& hi) {
    asm("mov.b64 {%0, %1}, %2;" : "=f"(lo), "=f"(hi) : "l"(v));
}

// ---------------- copy (self term of GIN aggregation) ----------------------
__global__ void copy_kernel(const float4* __restrict__ src, float4* __restrict__ dst, int n4) {
    int i = blockIdx.x * blockDim.x + threadIdx.x;
    if (i < n4) dst[i] = src[i];
}

// ---------------- edge scatter: agg[dst] += h[src] --------------------------
// one warp per edge; each lane handles one float4 (512B/row, fully coalesced)
__global__ void scatter_kernel(const float* __restrict__ h,
                               const int* __restrict__ srcI,
                               const int* __restrict__ dstI,
                               float* __restrict__ agg, int E) {
    int idx = blockIdx.x * blockDim.x + threadIdx.x;
    int e = idx >> 5;
    if (e >= E) return;
    int c = idx & 31;
    int s = __ldg(srcI + e);
    int d = __ldg(dstI + e);
    float4 v = ((const float4*)h)[s * 32 + c];
    float* p = agg + (size_t)d * 128 + c * 4;
    asm volatile("red.global.add.v4.f32 [%0], {%1, %2, %3, %4};"
                 :: "l"(p), "f"(v.x), "f"(v.y), "f"(v.z), "f"(v.w)
                 : "memory");
}

// ---------------- fused GEMM + bias + activation ----------------------------
// C[N,M] = act(A[N,128] @ W[128,M] + bias)
// ACT: 0 = none, 1 = relu, 2 = elu
// block: 256 threads, 64 rows x M cols; thread microtile 4 rows x TC cols.
template <int M, int ACT>
__global__ __launch_bounds__(256, 2)
void gemm_kernel(const float* __restrict__ A, const float* __restrict__ W,
                 const float* __restrict__ bias, float* __restrict__ C, int N) {
    constexpr int TC  = (M == 128) ? 8 : 4;   // cols per thread
    constexpr int NC2 = TC / 2;               // f32x2 pairs per thread

    extern __shared__ float smem[];
    float* sW = smem;              // [128][M]
    float* sA = smem + 128 * M;    // [64][128]

    int tid = threadIdx.x;

    // stage weights (full matrix) into smem
    for (int i = tid; i < 128 * M / 4; i += 256)
        ((float4*)sW)[i] = ((const float4*)W)[i];

    // stage 64-row A tile
    int row0 = blockIdx.x * 64;
    for (int i = tid; i < 64 * 128 / 4; i += 256) {
        int r  = i >> 5;          // 32 float4 per row
        int gr = row0 + r;
        ((float4*)sA)[i] = (gr < N) ? ((const float4*)A)[(size_t)gr * 32 + (i & 31)]
                                    : make_float4(0.f, 0.f, 0.f, 0.f);
    }
    __syncthreads();

    int tx = tid & 15;   // col group
    int ty = tid >> 4;   // row group

    unsigned long long acc[4][NC2];
#pragma unroll
    for (int r = 0; r < 4; r++)
#pragma unroll
        for (int c = 0; c < NC2; c++) acc[r][c] = pack2(0.f, 0.f);

    const float4* sA4 = (const float4*)sA;
    const float4* sW4 = (const float4*)sW;

#pragma unroll 8
    for (int k4 = 0; k4 < 32; k4++) {
        float4 av[4];
#pragma unroll
        for (int r = 0; r < 4; r++)
            av[r] = sA4[(ty * 4 + r) * 32 + k4];   // broadcast across tx

#pragma unroll
        for (int kk = 0; kk < 4; kk++) {
            int k = k4 * 4 + kk;
            unsigned long long wp[NC2];
            float4 w0 = sW4[(k * M + tx * TC) >> 2];
            wp[0] = pack2(w0.x, w0.y);
            wp[1] = pack2(w0.z, w0.w);
            if constexpr (NC2 == 4) {
                float4 w1 = sW4[((k * M + tx * TC) >> 2) + 1];
                wp[2] = pack2(w1.x, w1.y);
                wp[3] = pack2(w1.z, w1.w);
            }
#pragma unroll
            for (int r = 0; r < 4; r++) {
                float a = (kk == 0) ? av[r].x : (kk == 1) ? av[r].y
                        : (kk == 2) ? av[r].z : av[r].w;
                unsigned long long ad = pack2(a, a);
#pragma unroll
                for (int c = 0; c < NC2; c++)
                    acc[r][c] = fma2(ad, wp[c], acc[r][c]);
            }
        }
    }

    // epilogue: bias + activation + store
#pragma unroll
    for (int r = 0; r < 4; r++) {
        int gr = row0 + ty * 4 + r;
        if (gr >= N) continue;
        float out[TC];
#pragma unroll
        for (int c = 0; c < NC2; c++) unpack2(acc[r][c], out[2 * c], out[2 * c + 1]);
#pragma unroll
        for (int c = 0; c < TC; c++) {
            float v = out[c] + __ldg(bias + tx * TC + c);
            if (ACT == 1) v = fmaxf(v, 0.f);
            if (ACT == 2) v = (v > 0.f) ? v : expm1f(v);
            out[c] = v;
        }
        float* dst = C + (size_t)gr * M + tx * TC;
        ((float4*)dst)[0] = make_float4(out[0], out[1], out[2], out[3]);
        if constexpr (TC == 8)
            ((float4*)dst)[1] = make_float4(out[4], out[5], out[6], out[7]);
    }
}

// ---------------------------------------------------------------------------
extern "C" void kernel_launch(void* const* d_in, const int* in_sizes, int n_in,
                              void* d_out, int out_size) {
    const float* x   = (const float*)d_in[0];
    const float* Q   = (const float*)d_in[1];
    const float* w1a = (const float*)d_in[2];
    const float* b1a = (const float*)d_in[3];
    const float* w1b = (const float*)d_in[4];
    const float* b1b = (const float*)d_in[5];
    const float* w2a = (const float*)d_in[6];
    const float* b2a = (const float*)d_in[7];
    const float* w2b = (const float*)d_in[8];
    const float* b2b = (const float*)d_in[9];
    const int*   ei  = (const int*)d_in[10];

    int N = in_sizes[0] / 128;   // nodes
    int E = in_sizes[10] / 2;    // edges
    int C = in_sizes[9];         // num classes (b2b size)
    int qn = in_sizes[1];

    float* out = (float*)d_out;
    float* buf0; float* buf1;
    cudaGetSymbolAddress((void**)&buf0, g_buf0);
    cudaGetSymbolAddress((void**)&buf1, g_buf1);

    const int* srcI = ei;
    const int* dstI = ei + E;

    // opt-in shared memory sizes
    const int smem128 = (128 * 128 + 64 * 128) * (int)sizeof(float);  // 96 KB
    const int smem64  = (128 * 64  + 64 * 128) * (int)sizeof(float);  // 64 KB
    cudaFuncSetAttribute(gemm_kernel<128, 1>, cudaFuncAttributeMaxDynamicSharedMemorySize, smem128);
    cudaFuncSetAttribute(gemm_kernel<128, 2>, cudaFuncAttributeMaxDynamicSharedMemorySize, smem128);
    cudaFuncSetAttribute(gemm_kernel<64, 0>,  cudaFuncAttributeMaxDynamicSharedMemorySize, smem64);

    // Q pass-through
    cudaMemcpyAsync(out + (size_t)N * C, Q, (size_t)qn * sizeof(float),
                    cudaMemcpyDeviceToDevice, 0);

    int n4 = N * 32;
    int copyBlocks = (n4 + 255) / 256;
    int scatBlocks = (E * 32 + 255) / 256;
    int gemmBlocks = (N + 63) / 64;

    // layer 1
    copy_kernel<<<copyBlocks, 256>>>((const float4*)x, (float4*)buf0, n4);
    scatter_kernel<<<scatBlocks, 256>>>(x, srcI, dstI, buf0, E);
    gemm_kernel<128, 1><<<gemmBlocks, 256, smem128>>>(buf0, w1a, b1a, buf1, N);
    gemm_kernel<128, 2><<<gemmBlocks, 256, smem128>>>(buf1, w1b, b1b, buf0, N);

    // layer 2 (h lives in buf0)
    copy_kernel<<<copyBlocks, 256>>>((const float4*)buf0, (float4*)buf1, n4);
    scatter_kernel<<<scatBlocks, 256>>>(buf0, srcI, dstI, buf1, E);
    gemm_kernel<128, 1><<<gemmBlocks, 256, smem128>>>(buf1, w2a, b2a, buf0, N);
    gemm_kernel<64, 0><<<gemmBlocks, 256, smem64>>>(buf0, w2b, b2b, out, N);
}

// round 3
// speedup vs baseline: 1.3981x; 1.3981x over previous
#include <cuda_runtime.h>
#include <cstdint>
#include <math.h>

// ---------------------------------------------------------------------------
// GIN_Net forward on GB300 (sm_103a).
// GEMMs via mma.sync tf32 (base PTX — tcgen05 PTX is rejected by the harness's
// sm_103 ptxas target). Aggregation: copy + red.global.add scatter.
// ---------------------------------------------------------------------------

#define MAX_N 100000
#define HDIM  128

__device__ float g_buf0[MAX_N * HDIM];
__device__ float g_buf1[MAX_N * HDIM];
// transposed + tf32-rounded weights: w1a^T, w1b^T, w2a^T (128x128), w2b^T (64x128)
__device__ float g_wt[3 * 128 * 128 + 64 * 128];

__device__ __forceinline__ float tf32r(float x) {
    float y;
    asm("cvt.rna.tf32.f32 %0, %1;" : "=f"(y) : "f"(x));
    return y;
}

__device__ __forceinline__ void mma_tf32(float d[4], const uint32_t a[4],
                                         uint32_t b0, uint32_t b1) {
    asm volatile(
        "mma.sync.aligned.m16n8k8.row.col.f32.tf32.tf32.f32 "
        "{%0,%1,%2,%3}, {%4,%5,%6,%7}, {%8,%9}, {%0,%1,%2,%3};"
        : "+f"(d[0]), "+f"(d[1]), "+f"(d[2]), "+f"(d[3])
        : "r"(a[0]), "r"(a[1]), "r"(a[2]), "r"(a[3]), "r"(b0), "r"(b1));
}

// ---------------- small kernels ---------------------------------------------
__global__ void copy_kernel(const float4* __restrict__ src, float4* __restrict__ dst, int n4) {
    int i = blockIdx.x * blockDim.x + threadIdx.x;
    if (i < n4) dst[i] = src[i];
}

// Wt[n][k] = tf32_round(W[k][n]); W is [128][M], Wt is [M][128]
__global__ void transpose_tf32(const float* __restrict__ W, float* __restrict__ Wt, int M) {
    int i = blockIdx.x * blockDim.x + threadIdx.x;
    if (i >= M * 128) return;
    int n = i >> 7, k = i & 127;
    Wt[i] = tf32r(W[k * M + n]);
}

// agg[dst] += h[src] ; one warp per edge, lane per float4
__global__ void scatter_kernel(const float* __restrict__ h,
                               const int* __restrict__ srcI,
                               const int* __restrict__ dstI,
                               float* __restrict__ agg, int E) {
    int idx = blockIdx.x * blockDim.x + threadIdx.x;
    int e = idx >> 5;
    if (e >= E) return;
    int c = idx & 31;
    int s = __ldg(srcI + e);
    int d = __ldg(dstI + e);
    float4 v = ((const float4*)h)[s * 32 + c];
    float* p = agg + (size_t)d * 128 + c * 4;
    asm volatile("red.global.add.v4.f32 [%0], {%1, %2, %3, %4};"
                 :: "l"(p), "f"(v.x), "f"(v.y), "f"(v.z), "f"(v.w) : "memory");
}

// ---------------- tf32 mma.sync GEMM + bias + activation --------------------
// C[N, MOUT] = act(A[N,128] @ W[128,MOUT] + bias), Wt given as [MOUT][128].
// Block: 512 threads = 16 warps (8 row-groups x 2 col-groups), tile 256 x MOUT.
// Each warp: 32 rows x MOUT/2 cols via m16n8k8 fragments.
// ACT: 0=none, 1=relu, 2=elu.
#define PAD 132

template <int MOUT, int ACT>
__global__ __launch_bounds__(512, 1)
void mma_gemm(const float* __restrict__ A, const float* __restrict__ Wt,
              const float* __restrict__ bias, float* __restrict__ Cout, int N)
{
    constexpr int WN = MOUT / 2;   // cols per warp
    constexpr int NT = WN / 8;     // n-tiles per warp (8 or 4)

    extern __shared__ float smem[];
    float* sA    = smem;                    // [256][PAD]
    float* sW    = smem + 256 * PAD;        // [MOUT][PAD]
    float* sBias = sW + MOUT * PAD;         // [MOUT]

    const int tid  = threadIdx.x;
    const int row0 = blockIdx.x * 256;

    // stage Wt (already tf32-rounded)
    for (int i = tid; i < MOUT * 32; i += 512) {
        int n = i >> 5, k4 = i & 31;
        *(float4*)(sW + n * PAD + k4 * 4) = ((const float4*)Wt)[i];
    }
    // stage A tile with tf32 rounding
    for (int i = tid; i < 256 * 32; i += 512) {
        int r = i >> 5, k4 = i & 31;
        float4 v = make_float4(0.f, 0.f, 0.f, 0.f);
        if (row0 + r < N) v = ((const float4*)A)[(size_t)(row0 + r) * 32 + k4];
        v.x = tf32r(v.x); v.y = tf32r(v.y); v.z = tf32r(v.z); v.w = tf32r(v.w);
        *(float4*)(sA + r * PAD + k4 * 4) = v;
    }
    if (tid < MOUT) sBias[tid] = bias[tid];
    __syncthreads();

    const int wid    = tid >> 5;
    const int lane   = tid & 31;
    const int warp_n = wid >> 3;      // 0..1
    const int warp_m = wid & 7;       // 0..7
    const int gid    = lane >> 2;     // 0..7
    const int tig    = lane & 3;      // 0..3

    float d[2][NT][4];
#pragma unroll
    for (int mt = 0; mt < 2; mt++)
#pragma unroll
        for (int nt = 0; nt < NT; nt++)
#pragma unroll
            for (int j = 0; j < 4; j++) d[mt][nt][j] = 0.f;

    const uint32_t* sAu = (const uint32_t*)sA;
    const uint32_t* sWu = (const uint32_t*)sW;
    const int arow  = warp_m * 32 + gid;
    const int bcol0 = warp_n * WN;

#pragma unroll
    for (int kt = 0; kt < 16; kt++) {
        const int k0 = kt * 8 + tig;
        uint32_t a[2][4];
#pragma unroll
        for (int mt = 0; mt < 2; mt++) {
            int r = arow + mt * 16;
            a[mt][0] = sAu[r * PAD + k0];
            a[mt][1] = sAu[(r + 8) * PAD + k0];
            a[mt][2] = sAu[r * PAD + k0 + 4];
            a[mt][3] = sAu[(r + 8) * PAD + k0 + 4];
        }
#pragma unroll
        for (int nt = 0; nt < NT; nt++) {
            int n = bcol0 + nt * 8 + gid;
            uint32_t b0 = sWu[n * PAD + k0];
            uint32_t b1 = sWu[n * PAD + k0 + 4];
#pragma unroll
            for (int mt = 0; mt < 2; mt++)
                mma_tf32(d[mt][nt], a[mt], b0, b1);
        }
    }

    // epilogue: bias + activation + float2 stores
#pragma unroll
    for (int mt = 0; mt < 2; mt++) {
        int rbase = row0 + warp_m * 32 + mt * 16 + gid;
#pragma unroll
        for (int half = 0; half < 2; half++) {
            int r = rbase + half * 8;
            if (r < N) {
#pragma unroll
                for (int nt = 0; nt < NT; nt++) {
                    int col = bcol0 + nt * 8 + tig * 2;
                    float v0 = d[mt][nt][half * 2 + 0] + sBias[col];
                    float v1 = d[mt][nt][half * 2 + 1] + sBias[col + 1];
                    if (ACT == 1) { v0 = fmaxf(v0, 0.f); v1 = fmaxf(v1, 0.f); }
                    if (ACT == 2) {
                        v0 = (v0 > 0.f) ? v0 : expm1f(v0);
                        v1 = (v1 > 0.f) ? v1 : expm1f(v1);
                    }
                    *(float2*)(Cout + (size_t)r * MOUT + col) = make_float2(v0, v1);
                }
            }
        }
    }
}

// ---------------------------------------------------------------------------
extern "C" void kernel_launch(void* const* d_in, const int* in_sizes, int n_in,
                              void* d_out, int out_size) {
    const float* x   = (const float*)d_in[0];
    const float* Q   = (const float*)d_in[1];
    const float* w1a = (const float*)d_in[2];
    const float* b1a = (const float*)d_in[3];
    const float* w1b = (const float*)d_in[4];
    const float* b1b = (const float*)d_in[5];
    const float* w2a = (const float*)d_in[6];
    const float* b2a = (const float*)d_in[7];
    const float* w2b = (const float*)d_in[8];
    const float* b2b = (const float*)d_in[9];
    const int*   ei  = (const int*)d_in[10];

    int N = in_sizes[0] / 128;
    int E = in_sizes[10] / 2;
    int C = in_sizes[9];
    int qn = in_sizes[1];

    float* out = (float*)d_out;
    float *buf0, *buf1, *wt;
    cudaGetSymbolAddress((void**)&buf0, g_buf0);
    cudaGetSymbolAddress((void**)&buf1, g_buf1);
    cudaGetSymbolAddress((void**)&wt,   g_wt);
    float* wt1a = wt;
    float* wt1b = wt + 16384;
    float* wt2a = wt + 32768;
    float* wt2b = wt + 49152;

    const int* srcI = ei;
    const int* dstI = ei + E;

    const int smem128 = (256 * PAD + 128 * PAD + 128) * (int)sizeof(float);  // ~198.5 KB
    const int smem64  = (256 * PAD + 64 * PAD + 64)  * (int)sizeof(float);   // ~165 KB
    cudaFuncSetAttribute(mma_gemm<128, 1>, cudaFuncAttributeMaxDynamicSharedMemorySize, smem128);
    cudaFuncSetAttribute(mma_gemm<128, 2>, cudaFuncAttributeMaxDynamicSharedMemorySize, smem128);
    cudaFuncSetAttribute(mma_gemm<64, 0>,  cudaFuncAttributeMaxDynamicSharedMemorySize, smem64);

    // Q pass-through
    cudaMemcpyAsync(out + (size_t)N * C, Q, (size_t)qn * sizeof(float),
                    cudaMemcpyDeviceToDevice, 0);

    // weight transposes (tiny)
    transpose_tf32<<<64, 256>>>(w1a, wt1a, 128);
    transpose_tf32<<<64, 256>>>(w1b, wt1b, 128);
    transpose_tf32<<<64, 256>>>(w2a, wt2a, 128);
    transpose_tf32<<<32, 256>>>(w2b, wt2b, 64);

    int n4 = N * 32;
    int copyBlocks = (n4 + 255) / 256;
    int scatBlocks = (E * 32 + 255) / 256;
    int gemmBlocks = (N + 255) / 256;

    // layer 1
    copy_kernel<<<copyBlocks, 256>>>((const float4*)x, (float4*)buf0, n4);
    scatter_kernel<<<scatBlocks, 256>>>(x, srcI, dstI, buf0, E);
    mma_gemm<128, 1><<<gemmBlocks, 512, smem128>>>(buf0, wt1a, b1a, buf1, N);
    mma_gemm<128, 2><<<gemmBlocks, 512, smem128>>>(buf1, wt1b, b1b, buf0, N);

    // layer 2 (h in buf0)
    copy_kernel<<<copyBlocks, 256>>>((const float4*)buf0, (float4*)buf1, n4);
    scatter_kernel<<<scatBlocks, 256>>>(buf0, srcI, dstI, buf1, E);
    mma_gemm<128, 1><<<gemmBlocks, 512, smem128>>>(buf1, wt2a, b2a, buf0, N);
    mma_gemm<64, 0><<<gemmBlocks, 512, smem64>>>(buf0, wt2b, b2b, out, N);
}

// round 4
// speedup vs baseline: 1.9624x; 1.4037x over previous
#include <cuda_runtime.h>
#include <cstdint>
#include <math.h>

// ---------------------------------------------------------------------------
// GIN_Net forward on GB300 (sm_103a).
// GEMMs via mma.sync tf32. Aggregation via per-launch CSR build + warp gather
// (self term folded in; no copy kernels, no global atomics on feature data).
// ---------------------------------------------------------------------------

#define MAX_N 100000
#define MAX_E 1600000
#define HDIM  128

__device__ float g_buf0[MAX_N * HDIM];
__device__ float g_buf1[MAX_N * HDIM];
__device__ float g_wt[3 * 128 * 128 + 64 * 128];   // w1a^T,w1b^T,w2a^T,w2b^T (tf32-rounded)
__device__ int   g_adj[MAX_E];
__device__ int   g_rowStart[MAX_N + 1];
__device__ int   g_cursor[MAX_N];
__device__ int   g_deg[MAX_N];

__device__ __forceinline__ float tf32r(float x) {
    float y;
    asm("cvt.rna.tf32.f32 %0, %1;" : "=f"(y) : "f"(x));
    return y;
}

__device__ __forceinline__ void mma_tf32(float d[4], const uint32_t a[4],
                                         uint32_t b0, uint32_t b1) {
    asm volatile(
        "mma.sync.aligned.m16n8k8.row.col.f32.tf32.tf32.f32 "
        "{%0,%1,%2,%3}, {%4,%5,%6,%7}, {%8,%9}, {%0,%1,%2,%3};"
        : "+f"(d[0]), "+f"(d[1]), "+f"(d[2]), "+f"(d[3])
        : "r"(a[0]), "r"(a[1]), "r"(a[2]), "r"(a[3]), "r"(b0), "r"(b1));
}

// ---------------- CSR build -------------------------------------------------
__global__ void hist_kernel(const int* __restrict__ dst, int* __restrict__ deg, int E) {
    int e = blockIdx.x * blockDim.x + threadIdx.x;
    if (e < E) atomicAdd(&deg[dst[e]], 1);
}

// single-block prefix sum (warp-shuffle scan, 1024 threads)
__global__ void scan_kernel(const int* __restrict__ deg, int* __restrict__ rowStart,
                            int* __restrict__ cursor, int N) {
    __shared__ int warpSums[32];
    __shared__ int running;
    int tid = threadIdx.x, lane = tid & 31, wid = tid >> 5;
    if (tid == 0) running = 0;
    __syncthreads();
    for (int base = 0; base < N; base += 1024) {
        int i = base + tid;
        int v = (i < N) ? deg[i] : 0;
        int val = v;
#pragma unroll
        for (int off = 1; off < 32; off <<= 1) {
            int t = __shfl_up_sync(0xffffffffu, val, off);
            if (lane >= off) val += t;
        }
        if (lane == 31) warpSums[wid] = val;
        __syncthreads();
        if (wid == 0) {
            int w = warpSums[lane];
#pragma unroll
            for (int off = 1; off < 32; off <<= 1) {
                int t = __shfl_up_sync(0xffffffffu, w, off);
                if (lane >= off) w += t;
            }
            warpSums[lane] = w;   // inclusive warp-sum scan
        }
        __syncthreads();
        int warpExcl = (wid == 0) ? 0 : warpSums[wid - 1];
        int excl = running + warpExcl + val - v;
        if (i < N) { rowStart[i] = excl; cursor[i] = excl; }
        __syncthreads();
        if (tid == 0) running += warpSums[31];
        __syncthreads();
    }
    if (tid == 0) rowStart[N] = running;
}

__global__ void fill_kernel(const int* __restrict__ src, const int* __restrict__ dst,
                            int* __restrict__ cursor, int* __restrict__ adj, int E) {
    int e = blockIdx.x * blockDim.x + threadIdx.x;
    if (e < E) {
        int p = atomicAdd(&cursor[dst[e]], 1);
        adj[p] = src[e];
    }
}

// ---------------- CSR gather: out[n] = h[n] + sum_{nb in adj(n)} h[nb] ------
__device__ __forceinline__ void add4(float4& a, const float4 b) {
    a.x += b.x; a.y += b.y; a.z += b.z; a.w += b.w;
}

__global__ void gather_kernel(const float4* __restrict__ h4,
                              const int* __restrict__ rowStart,
                              const int* __restrict__ adj,
                              float4* __restrict__ out4, int N) {
    int warp = (blockIdx.x * blockDim.x + threadIdx.x) >> 5;
    int lane = threadIdx.x & 31;
    if (warp >= N) return;
    int s = __ldg(rowStart + warp);
    int e = __ldg(rowStart + warp + 1);
    float4 acc = h4[(size_t)warp * 32 + lane];   // self term
    int j = s;
    for (; j + 3 < e; j += 4) {
        int n0 = __ldg(adj + j),     n1 = __ldg(adj + j + 1);
        int n2 = __ldg(adj + j + 2), n3 = __ldg(adj + j + 3);
        float4 v0 = h4[(size_t)n0 * 32 + lane];
        float4 v1 = h4[(size_t)n1 * 32 + lane];
        float4 v2 = h4[(size_t)n2 * 32 + lane];
        float4 v3 = h4[(size_t)n3 * 32 + lane];
        add4(acc, v0); add4(acc, v1); add4(acc, v2); add4(acc, v3);
    }
    for (; j < e; j++) {
        int n0 = __ldg(adj + j);
        float4 v0 = h4[(size_t)n0 * 32 + lane];
        add4(acc, v0);
    }
    out4[(size_t)warp * 32 + lane] = acc;
}

// ---------------- weight transposes (all four in one launch) ----------------
// Wt[n][k] = tf32_round(W[k][n])
__global__ void transpose_all(const float* __restrict__ w1a, const float* __restrict__ w1b,
                              const float* __restrict__ w2a, const float* __restrict__ w2b,
                              float* __restrict__ wt) {
    int i = blockIdx.x * blockDim.x + threadIdx.x;   // 0 .. 57343
    if (i < 49152) {
        const float* W = (i < 16384) ? w1a : (i < 32768) ? w1b : w2a;
        int li = i & 16383;
        int n = li >> 7, k = li & 127;
        wt[i] = tf32r(W[k * 128 + n]);
    } else if (i < 57344) {
        int li = i - 49152;
        int n = li >> 7, k = li & 127;
        wt[i] = tf32r(w2b[k * 64 + n]);
    }
}

// ---------------- tf32 mma.sync GEMM + bias + activation --------------------
// C[N, MOUT] = act(A[N,128] @ W[128,MOUT] + bias), Wt given as [MOUT][128].
// Block: 512 threads = 16 warps (8 row-groups x 2 col-groups), tile 256 x MOUT.
// ACT: 0=none, 1=relu, 2=elu.
#define PAD 132

template <int MOUT, int ACT>
__global__ __launch_bounds__(512, 1)
void mma_gemm(const float* __restrict__ A, const float* __restrict__ Wt,
              const float* __restrict__ bias, float* __restrict__ Cout, int N)
{
    constexpr int WN = MOUT / 2;
    constexpr int NT = WN / 8;

    extern __shared__ float smem[];
    float* sA    = smem;                    // [256][PAD]
    float* sW    = smem + 256 * PAD;        // [MOUT][PAD]
    float* sBias = sW + MOUT * PAD;

    const int tid  = threadIdx.x;
    const int row0 = blockIdx.x * 256;

    for (int i = tid; i < MOUT * 32; i += 512) {
        int n = i >> 5, k4 = i & 31;
        *(float4*)(sW + n * PAD + k4 * 4) = ((const float4*)Wt)[i];
    }
    for (int i = tid; i < 256 * 32; i += 512) {
        int r = i >> 5, k4 = i & 31;
        float4 v = make_float4(0.f, 0.f, 0.f, 0.f);
        if (row0 + r < N) v = ((const float4*)A)[(size_t)(row0 + r) * 32 + k4];
        v.x = tf32r(v.x); v.y = tf32r(v.y); v.z = tf32r(v.z); v.w = tf32r(v.w);
        *(float4*)(sA + r * PAD + k4 * 4) = v;
    }
    if (tid < MOUT) sBias[tid] = bias[tid];
    __syncthreads();

    const int wid    = tid >> 5;
    const int lane   = tid & 31;
    const int warp_n = wid >> 3;
    const int warp_m = wid & 7;
    const int gid    = lane >> 2;
    const int tig    = lane & 3;

    float d[2][NT][4];
#pragma unroll
    for (int mt = 0; mt < 2; mt++)
#pragma unroll
        for (int nt = 0; nt < NT; nt++)
#pragma unroll
            for (int j = 0; j < 4; j++) d[mt][nt][j] = 0.f;

    const uint32_t* sAu = (const uint32_t*)sA;
    const uint32_t* sWu = (const uint32_t*)sW;
    const int arow  = warp_m * 32 + gid;
    const int bcol0 = warp_n * WN;

#pragma unroll
    for (int kt = 0; kt < 16; kt++) {
        const int k0 = kt * 8 + tig;
        uint32_t a[2][4];
#pragma unroll
        for (int mt = 0; mt < 2; mt++) {
            int r = arow + mt * 16;
            a[mt][0] = sAu[r * PAD + k0];
            a[mt][1] = sAu[(r + 8) * PAD + k0];
            a[mt][2] = sAu[r * PAD + k0 + 4];
            a[mt][3] = sAu[(r + 8) * PAD + k0 + 4];
        }
#pragma unroll
        for (int nt = 0; nt < NT; nt++) {
            int n = bcol0 + nt * 8 + gid;
            uint32_t b0 = sWu[n * PAD + k0];
            uint32_t b1 = sWu[n * PAD + k0 + 4];
#pragma unroll
            for (int mt = 0; mt < 2; mt++)
                mma_tf32(d[mt][nt], a[mt], b0, b1);
        }
    }

#pragma unroll
    for (int mt = 0; mt < 2; mt++) {
        int rbase = row0 + warp_m * 32 + mt * 16 + gid;
#pragma unroll
        for (int half = 0; half < 2; half++) {
            int r = rbase + half * 8;
            if (r < N) {
#pragma unroll
                for (int nt = 0; nt < NT; nt++) {
                    int col = bcol0 + nt * 8 + tig * 2;
                    float v0 = d[mt][nt][half * 2 + 0] + sBias[col];
                    float v1 = d[mt][nt][half * 2 + 1] + sBias[col + 1];
                    if (ACT == 1) { v0 = fmaxf(v0, 0.f); v1 = fmaxf(v1, 0.f); }
                    if (ACT == 2) {
                        v0 = (v0 > 0.f) ? v0 : expm1f(v0);
                        v1 = (v1 > 0.f) ? v1 : expm1f(v1);
                    }
                    *(float2*)(Cout + (size_t)r * MOUT + col) = make_float2(v0, v1);
                }
            }
        }
    }
}

// ---------------------------------------------------------------------------
extern "C" void kernel_launch(void* const* d_in, const int* in_sizes, int n_in,
                              void* d_out, int out_size) {
    const float* x   = (const float*)d_in[0];
    const float* Q   = (const float*)d_in[1];
    const float* w1a = (const float*)d_in[2];
    const float* b1a = (const float*)d_in[3];
    const float* w1b = (const float*)d_in[4];
    const float* b1b = (const float*)d_in[5];
    const float* w2a = (const float*)d_in[6];
    const float* b2a = (const float*)d_in[7];
    const float* w2b = (const float*)d_in[8];
    const float* b2b = (const float*)d_in[9];
    const int*   ei  = (const int*)d_in[10];

    int N = in_sizes[0] / 128;
    int E = in_sizes[10] / 2;
    int C = in_sizes[9];
    int qn = in_sizes[1];

    float* out = (float*)d_out;
    float *buf0, *buf1, *wt;
    int *adj, *rowStart, *cursor, *deg;
    cudaGetSymbolAddress((void**)&buf0, g_buf0);
    cudaGetSymbolAddress((void**)&buf1, g_buf1);
    cudaGetSymbolAddress((void**)&wt,   g_wt);
    cudaGetSymbolAddress((void**)&adj,      g_adj);
    cudaGetSymbolAddress((void**)&rowStart, g_rowStart);
    cudaGetSymbolAddress((void**)&cursor,   g_cursor);
    cudaGetSymbolAddress((void**)&deg,      g_deg);

    float* wt1a = wt;
    float* wt1b = wt + 16384;
    float* wt2a = wt + 32768;
    float* wt2b = wt + 49152;

    const int* srcI = ei;
    const int* dstI = ei + E;

    const int smem128 = (256 * PAD + 128 * PAD + 128) * (int)sizeof(float);
    const int smem64  = (256 * PAD + 64 * PAD + 64)  * (int)sizeof(float);
    cudaFuncSetAttribute(mma_gemm<128, 1>, cudaFuncAttributeMaxDynamicSharedMemorySize, smem128);
    cudaFuncSetAttribute(mma_gemm<128, 2>, cudaFuncAttributeMaxDynamicSharedMemorySize, smem128);
    cudaFuncSetAttribute(mma_gemm<64, 0>,  cudaFuncAttributeMaxDynamicSharedMemorySize, smem64);

    // Q pass-through
    cudaMemcpyAsync(out + (size_t)N * C, Q, (size_t)qn * sizeof(float),
                    cudaMemcpyDeviceToDevice, 0);

    // CSR build (per launch; deterministic up to neighbor order, same as atomics)
    cudaMemsetAsync(deg, 0, N * sizeof(int), 0);
    hist_kernel<<<(E + 255) / 256, 256>>>(dstI, deg, E);
    scan_kernel<<<1, 1024>>>(deg, rowStart, cursor, N);
    fill_kernel<<<(E + 255) / 256, 256>>>(srcI, dstI, cursor, adj, E);

    // weight transposes (one launch)
    transpose_all<<<(57344 + 255) / 256, 256>>>(w1a, w1b, w2a, w2b, wt);

    int gatBlocks  = (N * 32 + 255) / 256;
    int gemmBlocks = (N + 255) / 256;

    // layer 1
    gather_kernel<<<gatBlocks, 256>>>((const float4*)x, rowStart, adj, (float4*)buf0, N);
    mma_gemm<128, 1><<<gemmBlocks, 512, smem128>>>(buf0, wt1a, b1a, buf1, N);
    mma_gemm<128, 2><<<gemmBlocks, 512, smem128>>>(buf1, wt1b, b1b, buf0, N);

    // layer 2 (h in buf0)
    gather_kernel<<<gatBlocks, 256>>>((const float4*)buf0, rowStart, adj, (float4*)buf1, N);
    mma_gemm<128, 1><<<gemmBlocks, 512, smem128>>>(buf1, wt2a, b2a, buf0, N);
    mma_gemm<64, 0><<<gemmBlocks, 512, smem64>>>(buf0, wt2b, b2b, out, N);
}